// round 13
// baseline (speedup 1.0000x reference)
#include <cuda_runtime.h>
#include <cstdint>

typedef signed char s8;

#define BB 128
#define CC 64
#define HH_ 56
#define WW_ 56
#define HWP 3136
#define NELEM (BB*CC*HWP)       // 25690112
#define NWORDS (NELEM/4)        // 6422528

// ---------------- persistent device scratch ----------------
__device__ alignas(16) float g_out1[NELEM];     // stage1 output, NHWC fp32
__device__ alignas(16) int   g_xq[NWORDS];      // stage1 act k-plane, NHWC int8 (k in [-7,7])
__device__ alignas(16) int   g_xc[NWORDS];      // stage1 act c-plane (+-1 for |k| in {5,7})
__device__ alignas(16) int   g_x1[NWORDS];      // stage2 act k-plane
__device__ alignas(16) int   g_x1c[NWORDS];     // stage2 act c-plane
__device__ alignas(16) int   g_wgt1[3*48*64];   // packed +-1 int8, [kh][j][co]
__device__ alignas(16) int   g_wgt2[3*48*64];
__device__ float g_sw1[64], g_sw2[64];
__device__ float g_qw1[64], g_qb1[64], g_qw2[64], g_qb2[64];
__device__ float g_div7[15];                    // fl(k/7), k=-7..7
__device__ unsigned g_T1bits, g_T2bits;

#define CONV_SMEM_INTS (9216 + 2*2784)
#define CONV_SMEM_BYTES (CONV_SMEM_INTS*4)

__global__ void init_kernel() {
  g_T1bits = 0u; g_T2bits = 0u;
  #pragma unroll
  for (int k = -7; k <= 7; k++) g_div7[k+7] = __fdiv_rn((float)k, 7.f);
}

// ---------------- global abs-max over x ----------------
__global__ void absmax_kernel(const float* __restrict__ x) {
  const float4* x4 = (const float4*)x;
  float m = 0.f;
  for (int i = blockIdx.x*blockDim.x + threadIdx.x; i < NWORDS; i += gridDim.x*blockDim.x) {
    float4 v = x4[i];
    m = fmaxf(m, fmaxf(fmaxf(fabsf(v.x), fabsf(v.y)), fmaxf(fabsf(v.z), fabsf(v.w))));
  }
  #pragma unroll
  for (int o = 16; o; o >>= 1) m = fmaxf(m, __shfl_xor_sync(0xFFFFFFFFu, m, o));
  if ((threadIdx.x & 31) == 0) atomicMax(&g_T1bits, __float_as_uint(m));
}

// ---------------- helpers ----------------
__device__ __forceinline__ double warp_sumd(double v) {
  #pragma unroll
  for (int o = 16; o; o >>= 1) v += __shfl_xor_sync(0xFFFFFFFFu, v, o);
  return v;
}
__device__ __forceinline__ float warp_maxf(float v) {
  #pragma unroll
  for (int o = 16; o; o >>= 1) v = fmaxf(v, __shfl_xor_sync(0xFFFFFFFFu, v, o));
  return v;
}
__device__ __forceinline__ float quant_val(float x, float T, float n) {
  float c = fminf(fmaxf(x, -T), T);
  float r = __fdiv_rn(c, T);
  float q = __fdiv_rn(rintf(__fmul_rn(r, n)), n);
  return __fmul_rn(q, T);
}
// c-plane value: sign(k) if |k| in {5,7} else 0 (TF32(fl(k/7)) = (1170k + 2c)/8192)
__device__ __forceinline__ int cplane(int k) {
  int a = k < 0 ? -k : k;
  return (a == 5 || a == 7) ? (k > 0 ? 1 : -1) : 0;
}

// ---------------- weight + BN prep ----------------
__global__ void prep_kernel(const float* __restrict__ w1, const float* __restrict__ w2,
                            const float* __restrict__ g1, const float* __restrict__ b1,
                            const float* __restrict__ m1, const float* __restrict__ v1,
                            const float* __restrict__ g2, const float* __restrict__ b2,
                            const float* __restrict__ m2, const float* __restrict__ v2) {
  int wid = threadIdx.x >> 5, lane = threadIdx.x & 31;
  for (int pass = 0; pass < 2; pass++) {
    const float* wsrc = pass ? w2 : w1;
    int* wdst = pass ? g_wgt2 : g_wgt1;
    float* swdst = pass ? g_sw2 : g_sw1;
    for (int co = wid; co < 64; co += 16) {
      const float* w = wsrc + co*576;
      double s = 0.0;
      for (int i = lane; i < 576; i += 32) s += (double)w[i];
      s = warp_sumd(s);
      double mean = s / 576.0;
      double s2 = 0.0, sa = 0.0;
      for (int i = lane; i < 576; i += 32) {
        double d = (double)w[i] - mean; s2 += d*d; sa += fabs(d);
      }
      s2 = warp_sumd(s2); sa = warp_sumd(sa);
      double stdv = sqrt(s2 / 575.0);
      double mabs = (sa / 576.0) / stdv;            // mean |bw|
      if (lane == 0) swdst[co] = (float)exp2(rint(log2(mabs)));
      // sign-pack into dp4a layout: word = [kh][kw*16 + ci/4][co], bytes = ci%4
      for (int widx = lane; widx < 144; widx += 32) {
        int kh = widx / 48, rr = widx % 48, kw = rr >> 4, ci4 = (rr & 15) << 2;
        unsigned word = 0;
        #pragma unroll
        for (int bbb = 0; bbb < 4; bbb++) {
          double d = (double)w[(ci4+bbb)*9 + kh*3 + kw] - mean;
          unsigned byte = (d >= 0.0) ? 0x01u : 0xFFu;   // +1 / -1 as int8
          word |= byte << (8*bbb);
        }
        wdst[(kh*48 + kw*16 + (ci4 >> 2))*64 + co] = (int)word;
      }
    }
  }
  __syncthreads();
  // BN fold + quantize (fp32 op-for-op like JAX)
  if (wid < 2) {
    const float* gg = wid ? g2 : g1;
    const float* bt = wid ? b2 : b1;
    const float* mm = wid ? m2 : m1;
    const float* vv = wid ? v2 : v1;
    float* qwd = wid ? g_qw2 : g_qw1;
    float* qbd = wid ? g_qb2 : g_qb1;
    float wv[2], bv[2];
    float mw = 0.f, mb = 0.f;
    #pragma unroll
    for (int q = 0; q < 2; q++) {
      int c = lane + q*32;
      float stdv = __fsqrt_rn(__fadd_rn(vv[c], 1e-5f));
      float wq = __fdiv_rn(gg[c], stdv);
      float bq = __fsub_rn(bt[c], __fmul_rn(wq, mm[c]));
      wv[q] = wq; bv[q] = bq;
      mw = fmaxf(mw, fabsf(wq)); mb = fmaxf(mb, fabsf(bq));
    }
    mw = warp_maxf(mw); mb = warp_maxf(mb);
    float Tw = fminf(fmaxf(mw, 1e-10f), 255.f);
    float Tb = fminf(fmaxf(mb, 1e-10f), 255.f);
    #pragma unroll
    for (int q = 0; q < 2; q++) {
      int c = lane + q*32;
      qwd[c] = quant_val(wv[q], Tw, 7.f);
      qbd[c] = quant_val(bv[q], Tb, 4095.f);
    }
  }
}

// ---------------- quantize x + NCHW -> NHWC int8 (k-plane + c-plane) ----------------
__global__ void qtrans_kernel(const float* __restrict__ x) {
  __shared__ s8 sm[64][68];
  int n = blockIdx.y;
  int hw0 = blockIdx.x * 64;
  float T = fminf(fmaxf(__uint_as_float(g_T1bits), 1e-10f), 255.f);
  for (int i = threadIdx.x; i < 4096; i += 256) {
    int c = i >> 6, hwl = i & 63;
    float v = x[((size_t)n*CC + c)*HWP + hw0 + hwl];
    float cl = fminf(fmaxf(v, -T), T);
    int k = (int)rintf(__fmul_rn(__fdiv_rn(cl, T), 7.f));
    sm[hwl][c] = (s8)k;
  }
  __syncthreads();
  for (int i = threadIdx.x; i < 1024; i += 256) {
    int hwl = i >> 4, c4 = (i & 15) << 2;
    unsigned kw = 0, cw = 0;
    #pragma unroll
    for (int b = 0; b < 4; b++) {
      int kk = (int)sm[hwl][c4+b];            // s8: proper sign extension
      kw |= ((unsigned)kk & 255u) << (8*b);
      cw |= ((unsigned)cplane(kk) & 255u) << (8*b);
    }
    int idx = (n*HWP + hw0 + hwl)*16 + (c4 >> 2);
    g_xq[idx] = (int)kw;
    g_xc[idx] = (int)cw;
  }
}

// ---------------- conv (2-plane dp4a, exact TF32 emulation) + fused epilogue --------
template<int STAGE>
__global__ void __launch_bounds__(256) conv_kernel(float* __restrict__ outp) {
  extern __shared__ int s_dyn[];
  int* s_wgt = s_dyn;            // 9216 ints, [kh][j][co]
  int* s_k   = s_dyn + 9216;     // 3 rows * 58 px * 16 words (k-plane)
  int* s_c   = s_dyn + 12000;    // same (c-plane)
  int h = blockIdx.x, n = blockIdx.y;
  int t = threadIdx.x;
  const int*   actk = (STAGE == 1) ? g_xq   : g_x1;
  const int*   actc = (STAGE == 1) ? g_xc   : g_x1c;
  const int*   wgt  = (STAGE == 1) ? g_wgt1 : g_wgt2;
  const float* sw   = (STAGE == 1) ? g_sw1  : g_sw2;
  const float* qw   = (STAGE == 1) ? g_qw1  : g_qw2;
  const float* qb   = (STAGE == 1) ? g_qb1  : g_qb2;
  float* dst1 = (STAGE == 1) ? g_out1 : outp;

  { // weights -> smem
    const int4* wsrc = (const int4*)wgt;
    int4* wdv = (int4*)s_wgt;
    for (int i = t; i < 2304; i += 256) wdv[i] = wsrc[i];
  }
  int4 z4 = make_int4(0,0,0,0);
  #pragma unroll
  for (int r = 0; r < 3; r++) {
    int hr = h + r - 1;
    int4* dk = (int4*)(s_k + r*928);
    int4* dc = (int4*)(s_c + r*928);
    if (hr < 0 || hr >= HH_) {
      for (int i = t; i < 232; i += 256) { dk[i] = z4; dc[i] = z4; }
    } else {
      if (t < 4)   { dk[t] = z4; dc[t] = z4; }                         // left pad pixel
      if (t >= 252){ dk[228 + (t-252)] = z4; dc[228 + (t-252)] = z4; } // right pad
      const int4* sk_ = (const int4*)&actk[((size_t)n*HWP + hr*WW_)*16];
      const int4* sc_ = (const int4*)&actc[((size_t)n*HWP + hr*WW_)*16];
      for (int i = t; i < 224; i += 256) { dk[4+i] = sk_[i]; dc[4+i] = sc_[i]; }
    }
  }
  __syncthreads();

  int acck[4][4], accc[4][4];
  #pragma unroll
  for (int i = 0; i < 4; i++)
    #pragma unroll
    for (int c = 0; c < 4; c++) { acck[i][c] = 0; accc[i][c] = 0; }

  int co4 = (t & 15) << 2;
  int w0  = (t >> 4) << 2;
  float o[4][4];
  float lmax = 0.f;

  if (t < 224) {
    const int* apk = s_k + w0*16;
    const int* apc = s_c + w0*16;
    const int4* wp = (const int4*)s_wgt + (co4 >> 2);
    #pragma unroll
    for (int kh = 0; kh < 3; kh++) {
      const int* ak = apk + kh*928;
      const int* ac = apc + kh*928;
      const int4* wk = wp + kh*48*16;
      #pragma unroll 4
      for (int j = 0; j < 48; j++) {
        int4 wv = wk[j*16];
        int a0 = ak[j], a1 = ak[16+j], a2 = ak[32+j], a3 = ak[48+j];
        acck[0][0] = __dp4a(a0, wv.x, acck[0][0]);
        acck[0][1] = __dp4a(a0, wv.y, acck[0][1]);
        acck[0][2] = __dp4a(a0, wv.z, acck[0][2]);
        acck[0][3] = __dp4a(a0, wv.w, acck[0][3]);
        acck[1][0] = __dp4a(a1, wv.x, acck[1][0]);
        acck[1][1] = __dp4a(a1, wv.y, acck[1][1]);
        acck[1][2] = __dp4a(a1, wv.z, acck[1][2]);
        acck[1][3] = __dp4a(a1, wv.w, acck[1][3]);
        acck[2][0] = __dp4a(a2, wv.x, acck[2][0]);
        acck[2][1] = __dp4a(a2, wv.y, acck[2][1]);
        acck[2][2] = __dp4a(a2, wv.z, acck[2][2]);
        acck[2][3] = __dp4a(a2, wv.w, acck[2][3]);
        acck[3][0] = __dp4a(a3, wv.x, acck[3][0]);
        acck[3][1] = __dp4a(a3, wv.y, acck[3][1]);
        acck[3][2] = __dp4a(a3, wv.z, acck[3][2]);
        acck[3][3] = __dp4a(a3, wv.w, acck[3][3]);
        int c0 = ac[j], c1 = ac[16+j], c2 = ac[32+j], c3 = ac[48+j];
        accc[0][0] = __dp4a(c0, wv.x, accc[0][0]);
        accc[0][1] = __dp4a(c0, wv.y, accc[0][1]);
        accc[0][2] = __dp4a(c0, wv.z, accc[0][2]);
        accc[0][3] = __dp4a(c0, wv.w, accc[0][3]);
        accc[1][0] = __dp4a(c1, wv.x, accc[1][0]);
        accc[1][1] = __dp4a(c1, wv.y, accc[1][1]);
        accc[1][2] = __dp4a(c1, wv.z, accc[1][2]);
        accc[1][3] = __dp4a(c1, wv.w, accc[1][3]);
        accc[2][0] = __dp4a(c2, wv.x, accc[2][0]);
        accc[2][1] = __dp4a(c2, wv.y, accc[2][1]);
        accc[2][2] = __dp4a(c2, wv.z, accc[2][2]);
        accc[2][3] = __dp4a(c2, wv.w, accc[2][3]);
        accc[3][0] = __dp4a(c3, wv.x, accc[3][0]);
        accc[3][1] = __dp4a(c3, wv.y, accc[3][1]);
        accc[3][2] = __dp4a(c3, wv.z, accc[3][2]);
        accc[3][3] = __dp4a(c3, wv.w, accc[3][3]);
      }
    }
    // epilogue: y = sw * Su * 2^-13 (exact = TF32 conv); aq = round(y/576*1023)/1023*576;
    //           o = aq*qw + qb + k/7; clip to [-1,1]
    #pragma unroll
    for (int i = 0; i < 4; i++) {
      #pragma unroll
      for (int c = 0; c < 4; c++) {
        int co = co4 + c;
        int Su = 1170*acck[i][c] + 2*accc[i][c];
        float y = __fmul_rn((float)Su, __fmul_rn(sw[co], 0x1p-13f));
        float m = rintf(__fmul_rn(__fdiv_rn(y, 576.f), 1023.f));
        float aq = __fmul_rn(__fdiv_rn(m, 1023.f), 576.f);
        int wdv = s_k[928 + (w0 + i + 1)*16 + (co >> 2)];
        int k8 = (int)(s8)((wdv >> ((co & 3)*8)) & 0xFF);   // explicit sign extension
        float kv = g_div7[k8 + 7];
        float ov = __fadd_rn(__fadd_rn(__fmul_rn(aq, qw[co]), qb[co]), kv);
        ov = fminf(fmaxf(ov, -1.f), 1.f);
        o[i][c] = ov;
        lmax = fmaxf(lmax, fabsf(ov));
      }
    }
  }

  if (STAGE == 1) {
    if (t < 224) {
      #pragma unroll
      for (int i = 0; i < 4; i++) {
        float4 v = make_float4(o[i][0], o[i][1], o[i][2], o[i][3]);
        ((float4*)dst1)[(((size_t)n*HWP + h*WW_ + w0 + i)*64 + co4) >> 2] = v;
      }
    }
    lmax = warp_maxf(lmax);
    if ((t & 31) == 0) atomicMax(&g_T2bits, __float_as_uint(lmax));
  } else {
    __syncthreads();                       // everyone done reading s_wgt
    float* s_out = (float*)s_wgt;          // reuse: 64*57 floats
    if (t < 224) {
      #pragma unroll
      for (int i = 0; i < 4; i++)
        #pragma unroll
        for (int c = 0; c < 4; c++)
          s_out[(co4 + c)*57 + w0 + i] = o[i][c];
    }
    __syncthreads();
    for (int idx = t; idx < 3584; idx += 256) {
      int co = idx / 56, ww = idx % 56;
      dst1[(((size_t)n*CC + co)*HH_ + h)*WW_ + ww] = s_out[co*57 + ww];
    }
  }
}

// ---------------- quantize stage1 output -> int8 NHWC (both planes) ----------------
__global__ void quant2_kernel() {
  float T = fminf(fmaxf(__uint_as_float(g_T2bits), 1e-10f), 255.f);
  const float4* src = (const float4*)g_out1;
  for (int i = blockIdx.x*blockDim.x + threadIdx.x; i < NWORDS; i += gridDim.x*blockDim.x) {
    float4 v = src[i];
    int k0 = (int)rintf(__fmul_rn(__fdiv_rn(fminf(fmaxf(v.x, -T), T), T), 7.f));
    int k1 = (int)rintf(__fmul_rn(__fdiv_rn(fminf(fmaxf(v.y, -T), T), T), 7.f));
    int k2 = (int)rintf(__fmul_rn(__fdiv_rn(fminf(fmaxf(v.z, -T), T), T), 7.f));
    int k3 = (int)rintf(__fmul_rn(__fdiv_rn(fminf(fmaxf(v.w, -T), T), T), 7.f));
    g_x1[i]  = (k0 & 255) | ((k1 & 255) << 8) | ((k2 & 255) << 16) | ((k3 & 255) << 24);
    g_x1c[i] = (cplane(k0) & 255) | ((cplane(k1) & 255) << 8)
             | ((cplane(k2) & 255) << 16) | ((cplane(k3) & 255) << 24);
  }
}

// ---------------- launcher ----------------
extern "C" void kernel_launch(void* const* d_in, const int* in_sizes, int n_in,
                              void* d_out, int out_size) {
  const float* x  = (const float*)d_in[0];
  const float* w1 = (const float*)d_in[1];
  const float* w2 = (const float*)d_in[2];
  const float* g1 = (const float*)d_in[3];
  const float* b1 = (const float*)d_in[4];
  const float* m1 = (const float*)d_in[5];
  const float* v1 = (const float*)d_in[6];
  const float* g2 = (const float*)d_in[7];
  const float* b2 = (const float*)d_in[8];
  const float* m2 = (const float*)d_in[9];
  const float* v2 = (const float*)d_in[10];
  float* out = (float*)d_out;

  cudaFuncSetAttribute(conv_kernel<1>, cudaFuncAttributeMaxDynamicSharedMemorySize, CONV_SMEM_BYTES);
  cudaFuncSetAttribute(conv_kernel<2>, cudaFuncAttributeMaxDynamicSharedMemorySize, CONV_SMEM_BYTES);

  init_kernel<<<1, 1>>>();
  absmax_kernel<<<1024, 256>>>(x);
  prep_kernel<<<1, 512>>>(w1, w2, g1, b1, m1, v1, g2, b2, m2, v2);
  qtrans_kernel<<<dim3(49, BB), 256>>>(x);
  conv_kernel<1><<<dim3(HH_, BB), 256, CONV_SMEM_BYTES>>>(out);
  quant2_kernel<<<4096, 256>>>();
  conv_kernel<2><<<dim3(HH_, BB), 256, CONV_SMEM_BYTES>>>(out);
}